// round 15
// baseline (speedup 1.0000x reference)
#include <cuda_runtime.h>
#include <cuda_fp16.h>
#include <math.h>
#include <stdint.h>

#define B_    2
#define S_    1024
#define HID_  1024
#define NH_   16
#define HD_   64
#define HOT_  1024
#define COLD_ 3072
#define COMP_ 512
#define EPS_  1e-5f

// ---- async copy / ldmatrix helpers (compute_80-level PTX) ----
__device__ __forceinline__ uint32_t s2u(const void* p) {
    return (uint32_t)__cvta_generic_to_shared(p);
}
#define CP16(d, s) asm volatile("cp.async.cg.shared.global [%0], [%1], 16;" :: "r"(d), "l"(s))
#define CPC()      asm volatile("cp.async.commit_group;" ::: "memory")
#define CPW(n)     asm volatile("cp.async.wait_group %0;" :: "n"(n) : "memory")

__device__ __forceinline__ void ldsm4(uint32_t r[4], uint32_t a) {
    asm volatile("ldmatrix.sync.aligned.m8n8.x4.shared.b16 {%0,%1,%2,%3}, [%4];"
                 : "=r"(r[0]), "=r"(r[1]), "=r"(r[2]), "=r"(r[3]) : "r"(a));
}
__device__ __forceinline__ void ldsm4t(uint32_t r[4], uint32_t a) {
    asm volatile("ldmatrix.sync.aligned.m8n8.x4.trans.shared.b16 {%0,%1,%2,%3}, [%4];"
                 : "=r"(r[0]), "=r"(r[1]), "=r"(r[2]), "=r"(r[3]) : "r"(a));
}
__device__ __forceinline__ void mma_f16(float c[4],
    uint32_t a0, uint32_t a1, uint32_t a2, uint32_t a3,
    uint32_t b0, uint32_t b1)
{
    asm volatile(
        "mma.sync.aligned.m16n8k16.row.col.f32.f16.f16.f32 "
        "{%0,%1,%2,%3}, {%4,%5,%6,%7}, {%8,%9}, {%0,%1,%2,%3};"
        : "+f"(c[0]), "+f"(c[1]), "+f"(c[2]), "+f"(c[3])
        : "r"(a0), "r"(a1), "r"(a2), "r"(a3), "r"(b0), "r"(b1));
}
__device__ __forceinline__ uint32_t pkh2(float a, float b) {
    __half2 h = __floats2half2_rn(a, b);
    return *(uint32_t*)&h;
}
#define HADD2(d, a, b) asm("add.rn.f16x2 %0,%1,%2;" : "=r"(d) : "r"(a), "r"(b))
#define EX2H2(d, a)    asm("ex2.approx.f16x2 %0,%1;" : "=r"(d) : "r"(a))

#define K1_ 0.18033688011112042f   // 0.125 * log2(e)

// ---- scratch (half pipeline) ----
__device__ __half g_inh[B_ * S_ * HID_];
__device__ __half g_hkh[HOT_ * HID_];
__device__ __half g_hvh[HOT_ * HID_];
__device__ __half g_ckh[COLD_ * HID_];
__device__ __half g_cvh[COLD_ * HID_];
__device__ __half g_Wqh[HID_ * HID_];   // pre-scaled by K1
__device__ __half g_Wkh[HID_ * HID_];
__device__ __half g_Wvh[HID_ * HID_];
__device__ __half g_Woh[HID_ * HID_];
__device__ __half g_Wch[HID_ * COMP_];
__device__ __half g_Wdh[COMP_ * HID_];
__device__ __half g_Qh[B_ * S_ * HID_];
__device__ __half g_Khh[HOT_ * HID_];
__device__ __half g_Kch[COLD_ * HID_];
__device__ __half g_Vhh[HOT_ * HID_];
__device__ __half g_Cth[COLD_ * COMP_];
__device__ __half g_Vch[COLD_ * HID_];
__device__ __half g_bh2[HOT_];
__device__ __half g_bc2[COLD_];
__device__ __half g_Xh[B_ * S_ * HID_];
__device__ float  g_Y[B_ * S_ * HID_];

// ============================================================
// prep: fp32 -> fp16 conversion of inputs + weights (w/ scale)
// ============================================================
struct CvtSeg { const float* s; __half* d; int n4; float scl; };
struct CvtArgs { CvtSeg seg[11]; };

__global__ __launch_bounds__(256) void prep_cvt(CvtArgs a)
{
    int idx = blockIdx.x * 256 + threadIdx.x;
    #pragma unroll
    for (int i = 0; i < 11; i++) {
        if (idx < a.seg[i].n4) {
            float4 v = ((const float4*)a.seg[i].s)[idx];
            float s = a.seg[i].scl;
            uint2 u = {pkh2(v.x * s, v.y * s), pkh2(v.z * s, v.w * s)};
            ((uint2*)a.seg[i].d)[idx] = u;
            return;
        }
        idx -= a.seg[i].n4;
    }
}

__global__ __launch_bounds__(256) void bias_prep(
    const float* __restrict__ ha, const float* __restrict__ hc,
    const float* __restrict__ ca, const float* __restrict__ cc,
    __half* __restrict__ bh, __half* __restrict__ bc)
{
    const float L2E = 1.4426950408889634f;
    int i = blockIdx.x * 256 + threadIdx.x;
    if (i < HOT_)  bh[i] = __float2half(fmaf(-0.1f, ha[i], 0.05f * hc[i]) * L2E);
    if (i < COLD_) bc[i] = __float2half(fmaf(-0.1f, ca[i], 0.05f * cc[i]) * L2E);
}

// ============================================================
// cp.async 4-stage fp16 GEMM, 64x128 CTA tile (occupancy build):
// 8 warps, warp tile 32x32, ldmatrix + m16n8k16, 3 CTAs/SM.
// A stage: 64 rows x 48B; B stage: 16 rows x 272B.
// ============================================================
#define GA_ST 3072
#define GB_ST 4352

__device__ __forceinline__ void st2(__half* C, size_t off, float a, float b) {
    *(__half2*)(C + off) = __floats2half2_rn(a, b);
}
__device__ __forceinline__ void st2(float* C, size_t off, float a, float b) {
    *(float2*)(C + off) = make_float2(a, b);
}

__device__ __forceinline__ void g_fill(
    uint32_t asB, uint32_t bsB, int st, int k0,
    const __half* __restrict__ A, const __half* __restrict__ W,
    int N, int K, int bm, int bn, int tid)
{
    if (tid < 128) {
        int row = tid >> 1, ch = tid & 1;
        CP16(asB + st * GA_ST + row * 48 + ch * 16,
             A + (size_t)(bm + row) * K + k0 + ch * 8);
    }
    int kr = tid >> 4, bc = tid & 15;
    CP16(bsB + st * GB_ST + kr * 272 + bc * 16,
         W + (size_t)(k0 + kr) * N + bn + bc * 8);
}

template <typename OT>
__device__ __forceinline__ void gemm_cp_tile(
    const __half* __restrict__ A, const __half* __restrict__ W,
    const float* __restrict__ bias, float bscale, OT* __restrict__ C,
    int N, int K, int bm, int bn)
{
    __shared__ __align__(16) char As[4 * GA_ST];
    __shared__ __align__(16) char Bs[4 * GB_ST];
    const uint32_t asB = s2u(As);
    const uint32_t bsB = s2u(Bs);

    const int tid = threadIdx.x;
    const int wrp = tid >> 5, lane = tid & 31;
    const int lg = lane >> 2, lc = lane & 3;
    const int wm = (wrp & 1) * 32;
    const int wn = (wrp >> 1) * 32;
    const int kt = K >> 4;

    #pragma unroll
    for (int s = 0; s < 3; s++) {
        g_fill(asB, bsB, s, s * 16, A, W, N, K, bm, bn, tid);
        CPC();
    }

    float acc[8][4];
    #pragma unroll
    for (int i = 0; i < 8; i++)
        #pragma unroll
        for (int j = 0; j < 4; j++) acc[i][j] = 0.f;

    for (int k = 0; k < kt; k++) {
        CPW(2);
        __syncthreads();
        const int st = k & 3;
        if (k + 3 < kt)
            g_fill(asB, bsB, (k + 3) & 3, (k + 3) * 16, A, W, N, K, bm, bn, tid);
        CPC();

        const uint32_t aB = asB + st * GA_ST;
        const uint32_t bB = bsB + st * GB_ST;
        uint32_t af[2][4], bf[2][4];
        #pragma unroll
        for (int mt = 0; mt < 2; mt++)
            ldsm4(af[mt], aB + (wm + mt * 16 + (lane & 15)) * 48 + (lane >> 4) * 16);
        #pragma unroll
        for (int nt2 = 0; nt2 < 2; nt2++)
            ldsm4t(bf[nt2], bB + (lane & 15) * 272 + wn * 2 + nt2 * 32 + (lane >> 4) * 16);

        #pragma unroll
        for (int mt = 0; mt < 2; mt++)
            #pragma unroll
            for (int nt = 0; nt < 4; nt++)
                mma_f16(acc[mt * 4 + nt],
                        af[mt][0], af[mt][1], af[mt][2], af[mt][3],
                        bf[nt >> 1][(nt & 1) * 2], bf[nt >> 1][(nt & 1) * 2 + 1]);
    }

    #pragma unroll
    for (int nt = 0; nt < 4; nt++) {
        int col = bn + wn + nt * 8 + 2 * lc;
        float2 bv = *(const float2*)(bias + col);
        bv.x *= bscale; bv.y *= bscale;
        #pragma unroll
        for (int mt = 0; mt < 2; mt++) {
            float* c = acc[mt * 4 + nt];
            int row0 = bm + wm + mt * 16 + lg;
            st2(C, (size_t)row0 * N + col, c[0] + bv.x, c[1] + bv.y);
            st2(C, (size_t)(row0 + 8) * N + col, c[2] + bv.x, c[3] + bv.y);
        }
    }
}

struct ProjArgsH {
    const __half *inh, *hkh, *ckh, *hvh, *cvh;
    const __half *Wqh, *Wkh, *Wvh, *Wch;
    const float *bq, *bk, *bv, *bc;
    __half *Q, *Kh, *Kc, *Vh, *Ct;
};

// 64-row tiles: Q 256 | Khot 128 | Kcold 384 | Vhot 128 | Ct 192 = 1088
__global__ __launch_bounds__(256, 3) void proj_fused(ProjArgsH p)
{
    const int bid = blockIdx.x;
    const __half *A, *W; const float* bias; __half* C;
    int N = 1024, nb = 8, base;
    float bsc = 1.f;
    if (bid < 256)      { A = p.inh; W = p.Wqh; bias = p.bq; C = p.Q;  base = 0; bsc = K1_; }
    else if (bid < 384) { A = p.hkh; W = p.Wkh; bias = p.bk; C = p.Kh; base = 256; }
    else if (bid < 768) { A = p.ckh; W = p.Wkh; bias = p.bk; C = p.Kc; base = 384; }
    else if (bid < 896) { A = p.hvh; W = p.Wvh; bias = p.bv; C = p.Vh; base = 768; }
    else                { A = p.cvh; W = p.Wch; bias = p.bc; C = p.Ct; base = 896; N = 512; nb = 4; }
    const int loc = bid - base;
    gemm_cp_tile(A, W, bias, bsc, C, N, 1024, (loc / nb) * 64, (loc % nb) * 128);
}

template <typename OT>
__global__ __launch_bounds__(256, 3) void gemm_one(
    const __half* __restrict__ A, const __half* __restrict__ W,
    const float* __restrict__ bias, float bscale, OT* __restrict__ C,
    int N, int K, int nb)
{
    const int loc = blockIdx.x;
    gemm_cp_tile(A, W, bias, bscale, C, N, K, (loc / nb) * 64, (loc % nb) * 128);
}

// ============================================================
// Fused two-tier attention (best R12/R13 version, unchanged):
// 128 threads, 4 warps, warp tile M=32, chunk N=64, cp.async
// 2-stage, P in registers, f16x2 softmax, La via ones-mma.
// ============================================================
#define AT_K(s)  (18432 + (s) * 18688)
#define AT_V(s)  (AT_K(s) + 9216)
#define AT_BB(s) (AT_V(s) + 9216)
#define AT_BYTES (18432 + 2 * 18688)

#define NCH  ((HOT_ + COLD_) / 64)   // 64
#define HCH  (HOT_ / 64)             // 16

__device__ __forceinline__ void a_fill(
    uint32_t smb, int st,
    const __half* __restrict__ Kt, const __half* __restrict__ Vt,
    const __half* __restrict__ bias, int c0, int h, int tid)
{
    const uint32_t kB = smb + AT_K(st);
    const uint32_t vB = smb + AT_V(st);
    #pragma unroll
    for (int i = 0; i < 4; i++) {
        int lin = tid + i * 128;
        int r = lin >> 3, ch = lin & 7;
        size_t g = (size_t)(c0 + r) * HID_ + (size_t)h * HD_ + ch * 8;
        CP16(kB + r * 144 + ch * 16, Kt + g);
        CP16(vB + r * 144 + ch * 16, Vt + g);
    }
    if (tid < 8) CP16(smb + AT_BB(st) + tid * 16, bias + c0 + tid * 8);
}

__global__ __launch_bounds__(128, 2) void attn2(
    const __half* __restrict__ Q,
    const __half* __restrict__ Kh, const __half* __restrict__ Vh,
    const __half* __restrict__ Kc, const __half* __restrict__ Vc,
    const __half* __restrict__ bh, const __half* __restrict__ bc,
    __half* __restrict__ X)
{
    extern __shared__ char smc[];
    const uint32_t smb = s2u(smc);

    const int tid  = threadIdx.x;
    const int w    = tid >> 5;
    const int lane = tid & 31;
    const int lg   = lane >> 2;
    const int lc   = lane & 3;
    const uint32_t ONE2 = 0x3C003C00u;

    const int s0 = blockIdx.x * 128;
    const int h  = blockIdx.y;
    const int b  = blockIdx.z;
    const size_t qgbase = ((size_t)b * S_ + s0) * HID_ + (size_t)h * HD_;

    #pragma unroll
    for (int i = 0; i < 8; i++) {
        int lin = tid + i * 128;
        int r = lin >> 3, ch = lin & 7;
        CP16(smb + r * 144 + ch * 16, Q + qgbase + (size_t)r * HID_ + ch * 8);
    }
    a_fill(smb, 0, Kh, Vh, bh, 0, h, tid);
    CPC();

    float O[2][8][4];
    float La[2][4];
    #pragma unroll
    for (int mt = 0; mt < 2; mt++) {
        #pragma unroll
        for (int j = 0; j < 4; j++) La[mt][j] = 0.f;
        #pragma unroll
        for (int nt = 0; nt < 8; nt++)
            #pragma unroll
            for (int j = 0; j < 4; j++) O[mt][nt][j] = 0.f;
    }

    for (int gc = 0; gc < NCH; gc++) {
        const int st = gc & 1;
        CPW(0);
        __syncthreads();

        if (gc + 1 < NCH) {
            int n = gc + 1;
            bool t1 = n >= HCH;
            int cc = t1 ? n - HCH : n;
            a_fill(smb, n & 1, t1 ? Kc : Kh, t1 ? Vc : Vh,
                   t1 ? bc : bh, cc * 64, h, tid);
        }
        CPC();

        const uint32_t kB = smb + AT_K(st);
        const uint32_t vB = smb + AT_V(st);
        const uint32_t* biasS = (const uint32_t*)(smc + AT_BB(st));

        // ---- S = Q @ K^T  (Q pre-scaled by K1) ----
        float sc[2][8][4];
        #pragma unroll
        for (int mt = 0; mt < 2; mt++)
            #pragma unroll
            for (int nt = 0; nt < 8; nt++)
                #pragma unroll
                for (int j = 0; j < 4; j++) sc[mt][nt][j] = 0.f;

        #pragma unroll
        for (int kks = 0; kks < 4; kks++) {
            uint32_t aq[2][4];
            #pragma unroll
            for (int mt = 0; mt < 2; mt++)
                ldsm4(aq[mt], smb + (w * 32 + mt * 16 + (lane & 15)) * 144
                              + kks * 32 + (lane >> 4) * 16);
            #pragma unroll
            for (int nt2 = 0; nt2 < 4; nt2++) {
                uint32_t bk[4];
                ldsm4(bk, kB + (nt2 * 16 + (lane & 7) + ((lane >> 4) << 3)) * 144
                          + kks * 32 + ((lane >> 3) & 1) * 16);
                #pragma unroll
                for (int mt = 0; mt < 2; mt++) {
                    mma_f16(sc[mt][nt2 * 2],     aq[mt][0], aq[mt][1], aq[mt][2], aq[mt][3], bk[0], bk[1]);
                    mma_f16(sc[mt][nt2 * 2 + 1], aq[mt][0], aq[mt][1], aq[mt][2], aq[mt][3], bk[2], bk[3]);
                }
            }
        }

        // ---- softmax: pack -> add.f16x2(bias) -> ex2.f16x2 ----
        uint32_t pa[2][4][4];
        #pragma unroll
        for (int mt = 0; mt < 2; mt++) {
            #pragma unroll
            for (int nt = 0; nt < 8; nt++) {
                uint32_t bp = biasS[nt * 4 + lc];
                uint32_t u0 = pkh2(sc[mt][nt][0], sc[mt][nt][1]);
                uint32_t u1 = pkh2(sc[mt][nt][2], sc[mt][nt][3]);
                HADD2(u0, u0, bp);
                HADD2(u1, u1, bp);
                EX2H2(u0, u0);
                EX2H2(u1, u1);
                int j = nt >> 1;
                if ((nt & 1) == 0) { pa[mt][j][0] = u0; pa[mt][j][1] = u1; }
                else               { pa[mt][j][2] = u0; pa[mt][j][3] = u1; }
            }
        }

        // ---- row sums: La += P @ ones ----
        #pragma unroll
        for (int kks = 0; kks < 4; kks++)
            #pragma unroll
            for (int mt = 0; mt < 2; mt++)
                mma_f16(La[mt], pa[mt][kks][0], pa[mt][kks][1],
                        pa[mt][kks][2], pa[mt][kks][3], ONE2, ONE2);

        // ---- O += P @ V ----
        #pragma unroll
        for (int kks = 0; kks < 4; kks++) {
            #pragma unroll
            for (int nt2 = 0; nt2 < 4; nt2++) {
                uint32_t bv[4];
                ldsm4t(bv, vB + (kks * 16 + (lane & 15)) * 144
                           + nt2 * 32 + (lane >> 4) * 16);
                #pragma unroll
                for (int mt = 0; mt < 2; mt++) {
                    mma_f16(O[mt][nt2 * 2],     pa[mt][kks][0], pa[mt][kks][1], pa[mt][kks][2], pa[mt][kks][3], bv[0], bv[1]);
                    mma_f16(O[mt][nt2 * 2 + 1], pa[mt][kks][0], pa[mt][kks][1], pa[mt][kks][2], pa[mt][kks][3], bv[2], bv[3]);
                }
            }
        }

        // ---- tier finalize ----
        if (gc == HCH - 1 || gc == NCH - 1) {
            const int tier = (gc != HCH - 1);
            #pragma unroll
            for (int mt = 0; mt < 2; mt++) {
                float inv0 = 1.f / La[mt][0];
                float inv1 = 1.f / La[mt][2];
                size_t r0 = qgbase + (size_t)(w * 32 + mt * 16 + lg) * HID_ + 2 * lc;
                size_t r1 = r0 + 8 * HID_;
                #pragma unroll
                for (int nt = 0; nt < 8; nt++) {
                    float o0x = O[mt][nt][0] * inv0, o0y = O[mt][nt][1] * inv0;
                    float o1x = O[mt][nt][2] * inv1, o1y = O[mt][nt][3] * inv1;
                    if (tier) {
                        float2 f0 = __half22float2(*(__half2*)(X + r0 + nt * 8));
                        float2 f1 = __half22float2(*(__half2*)(X + r1 + nt * 8));
                        o0x += f0.x; o0y += f0.y;
                        o1x += f1.x; o1y += f1.y;
                    }
                    *(__half2*)(X + r0 + nt * 8) = __floats2half2_rn(o0x, o0y);
                    *(__half2*)(X + r1 + nt * 8) = __floats2half2_rn(o1x, o1y);
                }
                #pragma unroll
                for (int j = 0; j < 4; j++) La[mt][j] = 0.f;
                #pragma unroll
                for (int nt = 0; nt < 8; nt++)
                    #pragma unroll
                    for (int j = 0; j < 4; j++) O[mt][nt][j] = 0.f;
            }
        }
    }
}

// ============================================================
// LayerNorm
// ============================================================
__global__ __launch_bounds__(256) void ln_kernel(
    const float* __restrict__ Y, const float* __restrict__ gamma,
    const float* __restrict__ beta, float* __restrict__ out)
{
    __shared__ float red[16];
    const int row = blockIdx.x;
    const int tid = threadIdx.x;
    const float* y = Y + (size_t)row * HID_;

    float4 v = *(const float4*)(y + tid * 4);
    float sum = v.x + v.y + v.z + v.w;
    float sq  = v.x * v.x + v.y * v.y + v.z * v.z + v.w * v.w;
    #pragma unroll
    for (int o = 16; o > 0; o >>= 1) {
        sum += __shfl_xor_sync(0xffffffffu, sum, o);
        sq  += __shfl_xor_sync(0xffffffffu, sq, o);
    }
    if ((tid & 31) == 0) { red[tid >> 5] = sum; red[8 + (tid >> 5)] = sq; }
    __syncthreads();
    if (tid < 32) {
        float s = (tid < 8) ? red[tid] : 0.f;
        float q = (tid < 8) ? red[8 + tid] : 0.f;
        #pragma unroll
        for (int o = 4; o > 0; o >>= 1) {
            s += __shfl_xor_sync(0xffffffffu, s, o);
            q += __shfl_xor_sync(0xffffffffu, q, o);
        }
        if (tid == 0) { red[0] = s; red[1] = q; }
    }
    __syncthreads();
    float mu   = red[0] * (1.f / HID_);
    float var  = red[1] * (1.f / HID_) - mu * mu;
    float rstd = rsqrtf(var + EPS_);

    float4 g  = *(const float4*)(gamma + tid * 4);
    float4 bt = *(const float4*)(beta + tid * 4);
    float4 o;
    o.x = (v.x - mu) * rstd * g.x + bt.x;
    o.y = (v.y - mu) * rstd * g.y + bt.y;
    o.z = (v.z - mu) * rstd * g.z + bt.z;
    o.w = (v.w - mu) * rstd * g.w + bt.w;
    *(float4*)(out + (size_t)row * HID_ + tid * 4) = o;
}

// ============================================================
extern "C" void kernel_launch(void* const* d_in, const int* in_sizes, int n_in,
                              void* d_out, int out_size)
{
    const float* inputs      = (const float*)d_in[0];
    const float* hot_keys    = (const float*)d_in[1];
    const float* hot_values  = (const float*)d_in[2];
    const float* hot_age     = (const float*)d_in[3];
    const float* hot_access  = (const float*)d_in[4];
    const float* cold_keys   = (const float*)d_in[5];
    const float* cold_values = (const float*)d_in[6];
    const float* cold_age    = (const float*)d_in[7];
    const float* cold_access = (const float*)d_in[8];
    const float* Wq = (const float*)d_in[9];
    const float* bq = (const float*)d_in[10];
    const float* Wk = (const float*)d_in[11];
    const float* bk = (const float*)d_in[12];
    const float* Wv = (const float*)d_in[13];
    const float* bv = (const float*)d_in[14];
    const float* Wo = (const float*)d_in[15];
    const float* bo = (const float*)d_in[16];
    const float* Wc = (const float*)d_in[17];
    const float* bc = (const float*)d_in[18];
    const float* Wd = (const float*)d_in[19];
    const float* bd = (const float*)d_in[20];
    const float* gamma = (const float*)d_in[21];
    const float* beta  = (const float*)d_in[22];
    float* out = (float*)d_out;

    __half *inh, *hkh, *hvh, *ckh, *cvh;
    __half *Wqh, *Wkh, *Wvh, *Woh, *Wch, *Wdh;
    __half *Qh, *Khh, *Kch, *Vhh, *Cth, *Vch, *Xh;
    __half *bhp, *bcp;
    float *Yp;
    cudaGetSymbolAddress((void**)&inh, g_inh);
    cudaGetSymbolAddress((void**)&hkh, g_hkh);
    cudaGetSymbolAddress((void**)&hvh, g_hvh);
    cudaGetSymbolAddress((void**)&ckh, g_ckh);
    cudaGetSymbolAddress((void**)&cvh, g_cvh);
    cudaGetSymbolAddress((void**)&Wqh, g_Wqh);
    cudaGetSymbolAddress((void**)&Wkh, g_Wkh);
    cudaGetSymbolAddress((void**)&Wvh, g_Wvh);
    cudaGetSymbolAddress((void**)&Woh, g_Woh);
    cudaGetSymbolAddress((void**)&Wch, g_Wch);
    cudaGetSymbolAddress((void**)&Wdh, g_Wdh);
    cudaGetSymbolAddress((void**)&Qh,  g_Qh);
    cudaGetSymbolAddress((void**)&Khh, g_Khh);
    cudaGetSymbolAddress((void**)&Kch, g_Kch);
    cudaGetSymbolAddress((void**)&Vhh, g_Vhh);
    cudaGetSymbolAddress((void**)&Cth, g_Cth);
    cudaGetSymbolAddress((void**)&Vch, g_Vch);
    cudaGetSymbolAddress((void**)&bhp, g_bh2);
    cudaGetSymbolAddress((void**)&bcp, g_bc2);
    cudaGetSymbolAddress((void**)&Xh,  g_Xh);
    cudaGetSymbolAddress((void**)&Yp,  g_Y);

    cudaFuncSetAttribute(attn2, cudaFuncAttributeMaxDynamicSharedMemorySize,
                         AT_BYTES);

    // --- prep (Wq scaled by K1 so scores arrive pre-scaled for exp2) ---
    CvtArgs ca;
    ca.seg[0]  = {inputs,      inh, (B_ * S_ * HID_) / 4, 1.f};
    ca.seg[1]  = {hot_keys,    hkh, (HOT_ * HID_) / 4, 1.f};
    ca.seg[2]  = {hot_values,  hvh, (HOT_ * HID_) / 4, 1.f};
    ca.seg[3]  = {cold_keys,   ckh, (COLD_ * HID_) / 4, 1.f};
    ca.seg[4]  = {cold_values, cvh, (COLD_ * HID_) / 4, 1.f};
    ca.seg[5]  = {Wq, Wqh, (HID_ * HID_) / 4, K1_};
    ca.seg[6]  = {Wk, Wkh, (HID_ * HID_) / 4, 1.f};
    ca.seg[7]  = {Wv, Wvh, (HID_ * HID_) / 4, 1.f};
    ca.seg[8]  = {Wo, Woh, (HID_ * HID_) / 4, 1.f};
    ca.seg[9]  = {Wc, Wch, (HID_ * COMP_) / 4, 1.f};
    ca.seg[10] = {Wd, Wdh, (COMP_ * HID_) / 4, 1.f};
    int total4 = 0;
    for (int i = 0; i < 11; i++) total4 += ca.seg[i].n4;
    prep_cvt<<<(total4 + 255) / 256, 256>>>(ca);
    bias_prep<<<(COLD_ + 255) / 256, 256>>>(hot_age, hot_access,
                                            cold_age, cold_access, bhp, bcp);

    // --- projections (64-row tiles, 1088 CTAs) ---
    ProjArgsH pa;
    pa.inh = inh; pa.hkh = hkh; pa.ckh = ckh; pa.hvh = hvh; pa.cvh = cvh;
    pa.Wqh = Wqh; pa.Wkh = Wkh; pa.Wvh = Wvh; pa.Wch = Wch;
    pa.bq = bq; pa.bk = bk; pa.bv = bv; pa.bc = bc;
    pa.Q = Qh; pa.Kh = Khh; pa.Kc = Kch; pa.Vh = Vhh; pa.Ct = Cth;
    proj_fused<<<1088, 256>>>(pa);

    // --- Vcold = Ctmp @ Wd + bd (384 CTAs) ---
    gemm_one<__half><<<384, 256>>>(Cth, Wdh, bd, 1.f, Vch, 1024, 512, 8);

    // --- fused two-tier attention (best known) ---
    dim3 agrid(S_ / 128, NH_, B_);
    attn2<<<agrid, 128, AT_BYTES>>>(Qh, Khh, Vhh, Kch, Vch, bhp, bcp, Xh);

    // --- Y = X @ Wo + 2*bo (256 CTAs) ---
    gemm_one<float><<<256, 256>>>(Xh, Woh, bo, 2.f, Yp, 1024, 1024, 8);

    ln_kernel<<<B_ * S_, 256>>>(Yp, gamma, beta, out);
}

// round 16
// speedup vs baseline: 1.0540x; 1.0540x over previous
#include <cuda_runtime.h>
#include <cuda_fp16.h>
#include <math.h>
#include <stdint.h>

#define B_    2
#define S_    1024
#define HID_  1024
#define NH_   16
#define HD_   64
#define HOT_  1024
#define COLD_ 3072
#define COMP_ 512
#define EPS_  1e-5f

// ---- async copy / ldmatrix helpers (compute_80-level PTX) ----
__device__ __forceinline__ uint32_t s2u(const void* p) {
    return (uint32_t)__cvta_generic_to_shared(p);
}
#define CP16(d, s) asm volatile("cp.async.cg.shared.global [%0], [%1], 16;" :: "r"(d), "l"(s))
#define CPC()      asm volatile("cp.async.commit_group;" ::: "memory")
#define CPW(n)     asm volatile("cp.async.wait_group %0;" :: "n"(n) : "memory")

__device__ __forceinline__ void ldsm4(uint32_t r[4], uint32_t a) {
    asm volatile("ldmatrix.sync.aligned.m8n8.x4.shared.b16 {%0,%1,%2,%3}, [%4];"
                 : "=r"(r[0]), "=r"(r[1]), "=r"(r[2]), "=r"(r[3]) : "r"(a));
}
__device__ __forceinline__ void ldsm4t(uint32_t r[4], uint32_t a) {
    asm volatile("ldmatrix.sync.aligned.m8n8.x4.trans.shared.b16 {%0,%1,%2,%3}, [%4];"
                 : "=r"(r[0]), "=r"(r[1]), "=r"(r[2]), "=r"(r[3]) : "r"(a));
}
__device__ __forceinline__ void mma_f16(float c[4],
    uint32_t a0, uint32_t a1, uint32_t a2, uint32_t a3,
    uint32_t b0, uint32_t b1)
{
    asm volatile(
        "mma.sync.aligned.m16n8k16.row.col.f32.f16.f16.f32 "
        "{%0,%1,%2,%3}, {%4,%5,%6,%7}, {%8,%9}, {%0,%1,%2,%3};"
        : "+f"(c[0]), "+f"(c[1]), "+f"(c[2]), "+f"(c[3])
        : "r"(a0), "r"(a1), "r"(a2), "r"(a3), "r"(b0), "r"(b1));
}
__device__ __forceinline__ uint32_t pkh2(float a, float b) {
    __half2 h = __floats2half2_rn(a, b);
    return *(uint32_t*)&h;
}
#define HADD2(d, a, b) asm("add.rn.f16x2 %0,%1,%2;" : "=r"(d) : "r"(a), "r"(b))
#define EX2H2(d, a)    asm("ex2.approx.f16x2 %0,%1;" : "=r"(d) : "r"(a))

#define K1_ 0.18033688011112042f   // 0.125 * log2(e)

// ---- scratch (half pipeline) ----
__device__ __half g_inh[B_ * S_ * HID_];
__device__ __half g_hkh[HOT_ * HID_];
__device__ __half g_hvh[HOT_ * HID_];
__device__ __half g_ckh[COLD_ * HID_];
__device__ __half g_cvh[COLD_ * HID_];
__device__ __half g_Wqh[HID_ * HID_];   // pre-scaled by K1
__device__ __half g_Wkh[HID_ * HID_];
__device__ __half g_Wvh[HID_ * HID_];
__device__ __half g_Woh[HID_ * HID_];
__device__ __half g_Wch[HID_ * COMP_];
__device__ __half g_Wdh[COMP_ * HID_];
__device__ __half g_Qh[B_ * S_ * HID_];
__device__ __half g_Khh[HOT_ * HID_];
__device__ __half g_Kch[COLD_ * HID_];
__device__ __half g_Vhh[HOT_ * HID_];
__device__ __half g_Cth[COLD_ * COMP_];
__device__ __half g_Vch[COLD_ * HID_];
__device__ __half g_bh2[HOT_];
__device__ __half g_bc2[COLD_];
__device__ __half g_Xh[B_ * S_ * HID_];
__device__ float  g_Y[B_ * S_ * HID_];

// ============================================================
// prep: fp32 -> fp16 conversion of inputs + weights (w/ scale)
// + attention bias precompute, all in ONE launch
// ============================================================
struct CvtSeg { const float* s; __half* d; int n4; float scl; };
struct CvtArgs {
    CvtSeg seg[11];
    const float *ha, *hc, *ca, *cc;
    __half *bh, *bc;
};

__global__ __launch_bounds__(256) void prep_cvt(CvtArgs a)
{
    const float L2E = 1.4426950408889634f;
    int idx = blockIdx.x * 256 + threadIdx.x;
    #pragma unroll
    for (int i = 0; i < 11; i++) {
        if (idx < a.seg[i].n4) {
            float4 v = ((const float4*)a.seg[i].s)[idx];
            float s = a.seg[i].scl;
            uint2 u = {pkh2(v.x * s, v.y * s), pkh2(v.z * s, v.w * s)};
            ((uint2*)a.seg[i].d)[idx] = u;
            return;
        }
        idx -= a.seg[i].n4;
    }
    // hot bias (HOT_/4 quads)
    if (idx < HOT_ / 4) {
        float4 va = ((const float4*)a.ha)[idx];
        float4 vc = ((const float4*)a.hc)[idx];
        uint2 u = {pkh2(fmaf(-0.1f, va.x, 0.05f * vc.x) * L2E,
                        fmaf(-0.1f, va.y, 0.05f * vc.y) * L2E),
                   pkh2(fmaf(-0.1f, va.z, 0.05f * vc.z) * L2E,
                        fmaf(-0.1f, va.w, 0.05f * vc.w) * L2E)};
        ((uint2*)a.bh)[idx] = u;
        return;
    }
    idx -= HOT_ / 4;
    if (idx < COLD_ / 4) {
        float4 va = ((const float4*)a.ca)[idx];
        float4 vc = ((const float4*)a.cc)[idx];
        uint2 u = {pkh2(fmaf(-0.1f, va.x, 0.05f * vc.x) * L2E,
                        fmaf(-0.1f, va.y, 0.05f * vc.y) * L2E),
                   pkh2(fmaf(-0.1f, va.z, 0.05f * vc.z) * L2E,
                        fmaf(-0.1f, va.w, 0.05f * vc.w) * L2E)};
        ((uint2*)a.bc)[idx] = u;
    }
}

// ============================================================
// store helpers
// ============================================================
__device__ __forceinline__ void st2(__half* C, size_t off, float a, float b) {
    *(__half2*)(C + off) = __floats2half2_rn(a, b);
}
__device__ __forceinline__ void st2(float* C, size_t off, float a, float b) {
    *(float2*)(C + off) = make_float2(a, b);
}

// ============================================================
// GEMM tile A: 128x128x16 4-stage (R12 exact — best for proj)
// ============================================================
__device__ __forceinline__ void g_fill128(
    uint32_t asB, uint32_t bsB, int st, int k0,
    const __half* __restrict__ A, const __half* __restrict__ W,
    int N, int K, int bm, int bn, int tid)
{
    int row = tid >> 1, ch = tid & 1;
    CP16(asB + st * 6144 + row * 48 + ch * 16,
         A + (size_t)(bm + row) * K + k0 + ch * 8);
    int kr = tid >> 4, bc = tid & 15;
    CP16(bsB + st * 4352 + kr * 272 + bc * 16,
         W + (size_t)(k0 + kr) * N + bn + bc * 8);
}

template <typename OT>
__device__ __forceinline__ void gemm_tile128(
    const __half* __restrict__ A, const __half* __restrict__ W,
    const float* __restrict__ bias, float bscale, OT* __restrict__ C,
    int N, int K, int bm, int bn)
{
    __shared__ __align__(16) __half As[4][128 * 24];
    __shared__ __align__(16) __half Bs[4][16 * 136];
    const uint32_t asB = s2u(&As[0][0]);
    const uint32_t bsB = s2u(&Bs[0][0]);

    const int tid = threadIdx.x;
    const int wrp = tid >> 5, lane = tid & 31;
    const int lg = lane >> 2, lc = lane & 3;
    const int wm = (wrp & 3) * 32;
    const int wn = (wrp >> 2) * 64;
    const int kt = K >> 4;

    #pragma unroll
    for (int s = 0; s < 3; s++) {
        g_fill128(asB, bsB, s, s * 16, A, W, N, K, bm, bn, tid);
        CPC();
    }

    float acc[16][4];
    #pragma unroll
    for (int i = 0; i < 16; i++)
        #pragma unroll
        for (int j = 0; j < 4; j++) acc[i][j] = 0.f;

    for (int k = 0; k < kt; k++) {
        CPW(2);
        __syncthreads();
        const int st = k & 3;
        if (k + 3 < kt)
            g_fill128(asB, bsB, (k + 3) & 3, (k + 3) * 16, A, W, N, K, bm, bn, tid);
        CPC();

        const uint32_t aB = asB + st * 6144;
        const uint32_t bB = bsB + st * 4352;
        uint32_t af[2][4], bf[4][4];
        #pragma unroll
        for (int mt = 0; mt < 2; mt++)
            ldsm4(af[mt], aB + (wm + mt * 16 + (lane & 15)) * 48 + (lane >> 4) * 16);
        #pragma unroll
        for (int nt2 = 0; nt2 < 4; nt2++)
            ldsm4t(bf[nt2], bB + (lane & 15) * 272 + wn * 2 + nt2 * 32 + (lane >> 4) * 16);

        #pragma unroll
        for (int mt = 0; mt < 2; mt++)
            #pragma unroll
            for (int nt = 0; nt < 8; nt++)
                mma_f16(acc[mt * 8 + nt],
                        af[mt][0], af[mt][1], af[mt][2], af[mt][3],
                        bf[nt >> 1][(nt & 1) * 2], bf[nt >> 1][(nt & 1) * 2 + 1]);
    }

    #pragma unroll
    for (int nt = 0; nt < 8; nt++) {
        int col = bn + wn + nt * 8 + 2 * lc;
        float2 bv = *(const float2*)(bias + col);
        bv.x *= bscale; bv.y *= bscale;
        #pragma unroll
        for (int mt = 0; mt < 2; mt++) {
            float* c = acc[mt * 8 + nt];
            int row0 = bm + wm + mt * 16 + lg;
            st2(C, (size_t)row0 * N + col, c[0] + bv.x, c[1] + bv.y);
            st2(C, (size_t)(row0 + 8) * N + col, c[2] + bv.x, c[3] + bv.y);
        }
    }
}

// ============================================================
// GEMM tile B: 64x128x16 4-stage (R15 — best for Wd/Wo)
// ============================================================
#define GA_ST 3072
#define GB_ST 4352

__device__ __forceinline__ void g_fill64(
    uint32_t asB, uint32_t bsB, int st, int k0,
    const __half* __restrict__ A, const __half* __restrict__ W,
    int N, int K, int bm, int bn, int tid)
{
    if (tid < 128) {
        int row = tid >> 1, ch = tid & 1;
        CP16(asB + st * GA_ST + row * 48 + ch * 16,
             A + (size_t)(bm + row) * K + k0 + ch * 8);
    }
    int kr = tid >> 4, bc = tid & 15;
    CP16(bsB + st * GB_ST + kr * 272 + bc * 16,
         W + (size_t)(k0 + kr) * N + bn + bc * 8);
}

template <typename OT>
__device__ __forceinline__ void gemm_tile64(
    const __half* __restrict__ A, const __half* __restrict__ W,
    const float* __restrict__ bias, float bscale, OT* __restrict__ C,
    int N, int K, int bm, int bn)
{
    __shared__ __align__(16) char As[4 * GA_ST];
    __shared__ __align__(16) char Bs[4 * GB_ST];
    const uint32_t asB = s2u(As);
    const uint32_t bsB = s2u(Bs);

    const int tid = threadIdx.x;
    const int wrp = tid >> 5, lane = tid & 31;
    const int lg = lane >> 2, lc = lane & 3;
    const int wm = (wrp & 1) * 32;
    const int wn = (wrp >> 1) * 32;
    const int kt = K >> 4;

    #pragma unroll
    for (int s = 0; s < 3; s++) {
        g_fill64(asB, bsB, s, s * 16, A, W, N, K, bm, bn, tid);
        CPC();
    }

    float acc[8][4];
    #pragma unroll
    for (int i = 0; i < 8; i++)
        #pragma unroll
        for (int j = 0; j < 4; j++) acc[i][j] = 0.f;

    for (int k = 0; k < kt; k++) {
        CPW(2);
        __syncthreads();
        const int st = k & 3;
        if (k + 3 < kt)
            g_fill64(asB, bsB, (k + 3) & 3, (k + 3) * 16, A, W, N, K, bm, bn, tid);
        CPC();

        const uint32_t aB = asB + st * GA_ST;
        const uint32_t bB = bsB + st * GB_ST;
        uint32_t af[2][4], bf[2][4];
        #pragma unroll
        for (int mt = 0; mt < 2; mt++)
            ldsm4(af[mt], aB + (wm + mt * 16 + (lane & 15)) * 48 + (lane >> 4) * 16);
        #pragma unroll
        for (int nt2 = 0; nt2 < 2; nt2++)
            ldsm4t(bf[nt2], bB + (lane & 15) * 272 + wn * 2 + nt2 * 32 + (lane >> 4) * 16);

        #pragma unroll
        for (int mt = 0; mt < 2; mt++)
            #pragma unroll
            for (int nt = 0; nt < 4; nt++)
                mma_f16(acc[mt * 4 + nt],
                        af[mt][0], af[mt][1], af[mt][2], af[mt][3],
                        bf[nt >> 1][(nt & 1) * 2], bf[nt >> 1][(nt & 1) * 2 + 1]);
    }

    #pragma unroll
    for (int nt = 0; nt < 4; nt++) {
        int col = bn + wn + nt * 8 + 2 * lc;
        float2 bv = *(const float2*)(bias + col);
        bv.x *= bscale; bv.y *= bscale;
        #pragma unroll
        for (int mt = 0; mt < 2; mt++) {
            float* c = acc[mt * 4 + nt];
            int row0 = bm + wm + mt * 16 + lg;
            st2(C, (size_t)row0 * N + col, c[0] + bv.x, c[1] + bv.y);
            st2(C, (size_t)(row0 + 8) * N + col, c[2] + bv.x, c[3] + bv.y);
        }
    }
}

struct ProjArgsH {
    const __half *inh, *hkh, *ckh, *hvh, *cvh;
    const __half *Wqh, *Wkh, *Wvh, *Wch;
    const float *bq, *bk, *bv, *bc;
    __half *Q, *Kh, *Kc, *Vh, *Ct;
};

// 128-row tiles: Q 128 | Khot 64 | Kcold 192 | Vhot 64 | Ct 96 = 544
__global__ __launch_bounds__(256, 2) void proj_fused(ProjArgsH p)
{
    const int bid = blockIdx.x;
    const __half *A, *W; const float* bias; __half* C;
    int N = 1024, nb = 8, base;
    float bsc = 1.f;
    if (bid < 128)      { A = p.inh; W = p.Wqh; bias = p.bq; C = p.Q;  base = 0; bsc = K1_; }
    else if (bid < 192) { A = p.hkh; W = p.Wkh; bias = p.bk; C = p.Kh; base = 128; }
    else if (bid < 384) { A = p.ckh; W = p.Wkh; bias = p.bk; C = p.Kc; base = 192; }
    else if (bid < 448) { A = p.hvh; W = p.Wvh; bias = p.bv; C = p.Vh; base = 384; }
    else                { A = p.cvh; W = p.Wch; bias = p.bc; C = p.Ct; base = 448; N = 512; nb = 4; }
    const int loc = bid - base;
    gemm_tile128(A, W, bias, bsc, C, N, 1024, (loc / nb) * 128, (loc % nb) * 128);
}

template <typename OT>
__global__ __launch_bounds__(256, 3) void gemm_one64(
    const __half* __restrict__ A, const __half* __restrict__ W,
    const float* __restrict__ bias, float bscale, OT* __restrict__ C,
    int N, int K, int nb)
{
    const int loc = blockIdx.x;
    gemm_tile64(A, W, bias, bscale, C, N, K, (loc / nb) * 64, (loc % nb) * 128);
}

// ============================================================
// Fused two-tier attention (frozen best: R12/R13 kernel)
// ============================================================
#define AT_K(s)  (18432 + (s) * 18688)
#define AT_V(s)  (AT_K(s) + 9216)
#define AT_BB(s) (AT_V(s) + 9216)
#define AT_BYTES (18432 + 2 * 18688)

#define NCH  ((HOT_ + COLD_) / 64)   // 64
#define HCH  (HOT_ / 64)             // 16

__device__ __forceinline__ void a_fill(
    uint32_t smb, int st,
    const __half* __restrict__ Kt, const __half* __restrict__ Vt,
    const __half* __restrict__ bias, int c0, int h, int tid)
{
    const uint32_t kB = smb + AT_K(st);
    const uint32_t vB = smb + AT_V(st);
    #pragma unroll
    for (int i = 0; i < 4; i++) {
        int lin = tid + i * 128;
        int r = lin >> 3, ch = lin & 7;
        size_t g = (size_t)(c0 + r) * HID_ + (size_t)h * HD_ + ch * 8;
        CP16(kB + r * 144 + ch * 16, Kt + g);
        CP16(vB + r * 144 + ch * 16, Vt + g);
    }
    if (tid < 8) CP16(smb + AT_BB(st) + tid * 16, bias + c0 + tid * 8);
}

__global__ __launch_bounds__(128, 2) void attn2(
    const __half* __restrict__ Q,
    const __half* __restrict__ Kh, const __half* __restrict__ Vh,
    const __half* __restrict__ Kc, const __half* __restrict__ Vc,
    const __half* __restrict__ bh, const __half* __restrict__ bc,
    __half* __restrict__ X)
{
    extern __shared__ char smc[];
    const uint32_t smb = s2u(smc);

    const int tid  = threadIdx.x;
    const int w    = tid >> 5;
    const int lane = tid & 31;
    const int lg   = lane >> 2;
    const int lc   = lane & 3;
    const uint32_t ONE2 = 0x3C003C00u;

    const int s0 = blockIdx.x * 128;
    const int h  = blockIdx.y;
    const int b  = blockIdx.z;
    const size_t qgbase = ((size_t)b * S_ + s0) * HID_ + (size_t)h * HD_;

    #pragma unroll
    for (int i = 0; i < 8; i++) {
        int lin = tid + i * 128;
        int r = lin >> 3, ch = lin & 7;
        CP16(smb + r * 144 + ch * 16, Q + qgbase + (size_t)r * HID_ + ch * 8);
    }
    a_fill(smb, 0, Kh, Vh, bh, 0, h, tid);
    CPC();

    float O[2][8][4];
    float La[2][4];
    #pragma unroll
    for (int mt = 0; mt < 2; mt++) {
        #pragma unroll
        for (int j = 0; j < 4; j++) La[mt][j] = 0.f;
        #pragma unroll
        for (int nt = 0; nt < 8; nt++)
            #pragma unroll
            for (int j = 0; j < 4; j++) O[mt][nt][j] = 0.f;
    }

    for (int gc = 0; gc < NCH; gc++) {
        const int st = gc & 1;
        CPW(0);
        __syncthreads();

        if (gc + 1 < NCH) {
            int n = gc + 1;
            bool t1 = n >= HCH;
            int cc = t1 ? n - HCH : n;
            a_fill(smb, n & 1, t1 ? Kc : Kh, t1 ? Vc : Vh,
                   t1 ? bc : bh, cc * 64, h, tid);
        }
        CPC();

        const uint32_t kB = smb + AT_K(st);
        const uint32_t vB = smb + AT_V(st);
        const uint32_t* biasS = (const uint32_t*)(smc + AT_BB(st));

        // ---- S = Q @ K^T  (Q pre-scaled by K1) ----
        float sc[2][8][4];
        #pragma unroll
        for (int mt = 0; mt < 2; mt++)
            #pragma unroll
            for (int nt = 0; nt < 8; nt++)
                #pragma unroll
                for (int j = 0; j < 4; j++) sc[mt][nt][j] = 0.f;

        #pragma unroll
        for (int kks = 0; kks < 4; kks++) {
            uint32_t aq[2][4];
            #pragma unroll
            for (int mt = 0; mt < 2; mt++)
                ldsm4(aq[mt], smb + (w * 32 + mt * 16 + (lane & 15)) * 144
                              + kks * 32 + (lane >> 4) * 16);
            #pragma unroll
            for (int nt2 = 0; nt2 < 4; nt2++) {
                uint32_t bk[4];
                ldsm4(bk, kB + (nt2 * 16 + (lane & 7) + ((lane >> 4) << 3)) * 144
                          + kks * 32 + ((lane >> 3) & 1) * 16);
                #pragma unroll
                for (int mt = 0; mt < 2; mt++) {
                    mma_f16(sc[mt][nt2 * 2],     aq[mt][0], aq[mt][1], aq[mt][2], aq[mt][3], bk[0], bk[1]);
                    mma_f16(sc[mt][nt2 * 2 + 1], aq[mt][0], aq[mt][1], aq[mt][2], aq[mt][3], bk[2], bk[3]);
                }
            }
        }

        // ---- softmax: pack -> add.f16x2(bias) -> ex2.f16x2 ----
        uint32_t pa[2][4][4];
        #pragma unroll
        for (int mt = 0; mt < 2; mt++) {
            #pragma unroll
            for (int nt = 0; nt < 8; nt++) {
                uint32_t bp = biasS[nt * 4 + lc];
                uint32_t u0 = pkh2(sc[mt][nt][0], sc[mt][nt][1]);
                uint32_t u1 = pkh2(sc[mt][nt][2], sc[mt][nt][3]);
                HADD2(u0, u0, bp);
                HADD2(u1, u1, bp);
                EX2H2(u0, u0);
                EX2H2(u1, u1);
                int j = nt >> 1;
                if ((nt & 1) == 0) { pa[mt][j][0] = u0; pa[mt][j][1] = u1; }
                else               { pa[mt][j][2] = u0; pa[mt][j][3] = u1; }
            }
        }

        // ---- row sums: La += P @ ones ----
        #pragma unroll
        for (int kks = 0; kks < 4; kks++)
            #pragma unroll
            for (int mt = 0; mt < 2; mt++)
                mma_f16(La[mt], pa[mt][kks][0], pa[mt][kks][1],
                        pa[mt][kks][2], pa[mt][kks][3], ONE2, ONE2);

        // ---- O += P @ V ----
        #pragma unroll
        for (int kks = 0; kks < 4; kks++) {
            #pragma unroll
            for (int nt2 = 0; nt2 < 4; nt2++) {
                uint32_t bv[4];
                ldsm4t(bv, vB + (kks * 16 + (lane & 15)) * 144
                           + nt2 * 32 + (lane >> 4) * 16);
                #pragma unroll
                for (int mt = 0; mt < 2; mt++) {
                    mma_f16(O[mt][nt2 * 2],     pa[mt][kks][0], pa[mt][kks][1], pa[mt][kks][2], pa[mt][kks][3], bv[0], bv[1]);
                    mma_f16(O[mt][nt2 * 2 + 1], pa[mt][kks][0], pa[mt][kks][1], pa[mt][kks][2], pa[mt][kks][3], bv[2], bv[3]);
                }
            }
        }

        // ---- tier finalize ----
        if (gc == HCH - 1 || gc == NCH - 1) {
            const int tier = (gc != HCH - 1);
            #pragma unroll
            for (int mt = 0; mt < 2; mt++) {
                float inv0 = 1.f / La[mt][0];
                float inv1 = 1.f / La[mt][2];
                size_t r0 = qgbase + (size_t)(w * 32 + mt * 16 + lg) * HID_ + 2 * lc;
                size_t r1 = r0 + 8 * HID_;
                #pragma unroll
                for (int nt = 0; nt < 8; nt++) {
                    float o0x = O[mt][nt][0] * inv0, o0y = O[mt][nt][1] * inv0;
                    float o1x = O[mt][nt][2] * inv1, o1y = O[mt][nt][3] * inv1;
                    if (tier) {
                        float2 f0 = __half22float2(*(__half2*)(X + r0 + nt * 8));
                        float2 f1 = __half22float2(*(__half2*)(X + r1 + nt * 8));
                        o0x += f0.x; o0y += f0.y;
                        o1x += f1.x; o1y += f1.y;
                    }
                    *(__half2*)(X + r0 + nt * 8) = __floats2half2_rn(o0x, o0y);
                    *(__half2*)(X + r1 + nt * 8) = __floats2half2_rn(o1x, o1y);
                }
                #pragma unroll
                for (int j = 0; j < 4; j++) La[mt][j] = 0.f;
                #pragma unroll
                for (int nt = 0; nt < 8; nt++)
                    #pragma unroll
                    for (int j = 0; j < 4; j++) O[mt][nt][j] = 0.f;
            }
        }
    }
}

// ============================================================
// LayerNorm
// ============================================================
__global__ __launch_bounds__(256) void ln_kernel(
    const float* __restrict__ Y, const float* __restrict__ gamma,
    const float* __restrict__ beta, float* __restrict__ out)
{
    __shared__ float red[16];
    const int row = blockIdx.x;
    const int tid = threadIdx.x;
    const float* y = Y + (size_t)row * HID_;

    float4 v = *(const float4*)(y + tid * 4);
    float sum = v.x + v.y + v.z + v.w;
    float sq  = v.x * v.x + v.y * v.y + v.z * v.z + v.w * v.w;
    #pragma unroll
    for (int o = 16; o > 0; o >>= 1) {
        sum += __shfl_xor_sync(0xffffffffu, sum, o);
        sq  += __shfl_xor_sync(0xffffffffu, sq, o);
    }
    if ((tid & 31) == 0) { red[tid >> 5] = sum; red[8 + (tid >> 5)] = sq; }
    __syncthreads();
    if (tid < 32) {
        float s = (tid < 8) ? red[tid] : 0.f;
        float q = (tid < 8) ? red[8 + tid] : 0.f;
        #pragma unroll
        for (int o = 4; o > 0; o >>= 1) {
            s += __shfl_xor_sync(0xffffffffu, s, o);
            q += __shfl_xor_sync(0xffffffffu, q, o);
        }
        if (tid == 0) { red[0] = s; red[1] = q; }
    }
    __syncthreads();
    float mu   = red[0] * (1.f / HID_);
    float var  = red[1] * (1.f / HID_) - mu * mu;
    float rstd = rsqrtf(var + EPS_);

    float4 g  = *(const float4*)(gamma + tid * 4);
    float4 bt = *(const float4*)(beta + tid * 4);
    float4 o;
    o.x = (v.x - mu) * rstd * g.x + bt.x;
    o.y = (v.y - mu) * rstd * g.y + bt.y;
    o.z = (v.z - mu) * rstd * g.z + bt.z;
    o.w = (v.w - mu) * rstd * g.w + bt.w;
    *(float4*)(out + (size_t)row * HID_ + tid * 4) = o;
}

// ============================================================
extern "C" void kernel_launch(void* const* d_in, const int* in_sizes, int n_in,
                              void* d_out, int out_size)
{
    const float* inputs      = (const float*)d_in[0];
    const float* hot_keys    = (const float*)d_in[1];
    const float* hot_values  = (const float*)d_in[2];
    const float* hot_age     = (const float*)d_in[3];
    const float* hot_access  = (const float*)d_in[4];
    const float* cold_keys   = (const float*)d_in[5];
    const float* cold_values = (const float*)d_in[6];
    const float* cold_age    = (const float*)d_in[7];
    const float* cold_access = (const float*)d_in[8];
    const float* Wq = (const float*)d_in[9];
    const float* bq = (const float*)d_in[10];
    const float* Wk = (const float*)d_in[11];
    const float* bk = (const float*)d_in[12];
    const float* Wv = (const float*)d_in[13];
    const float* bv = (const float*)d_in[14];
    const float* Wo = (const float*)d_in[15];
    const float* bo = (const float*)d_in[16];
    const float* Wc = (const float*)d_in[17];
    const float* bc = (const float*)d_in[18];
    const float* Wd = (const float*)d_in[19];
    const float* bd = (const float*)d_in[20];
    const float* gamma = (const float*)d_in[21];
    const float* beta  = (const float*)d_in[22];
    float* out = (float*)d_out;

    __half *inh, *hkh, *hvh, *ckh, *cvh;
    __half *Wqh, *Wkh, *Wvh, *Woh, *Wch, *Wdh;
    __half *Qh, *Khh, *Kch, *Vhh, *Cth, *Vch, *Xh;
    __half *bhp, *bcp;
    float *Yp;
    cudaGetSymbolAddress((void**)&inh, g_inh);
    cudaGetSymbolAddress((void**)&hkh, g_hkh);
    cudaGetSymbolAddress((void**)&hvh, g_hvh);
    cudaGetSymbolAddress((void**)&ckh, g_ckh);
    cudaGetSymbolAddress((void**)&cvh, g_cvh);
    cudaGetSymbolAddress((void**)&Wqh, g_Wqh);
    cudaGetSymbolAddress((void**)&Wkh, g_Wkh);
    cudaGetSymbolAddress((void**)&Wvh, g_Wvh);
    cudaGetSymbolAddress((void**)&Woh, g_Woh);
    cudaGetSymbolAddress((void**)&Wch, g_Wch);
    cudaGetSymbolAddress((void**)&Wdh, g_Wdh);
    cudaGetSymbolAddress((void**)&Qh,  g_Qh);
    cudaGetSymbolAddress((void**)&Khh, g_Khh);
    cudaGetSymbolAddress((void**)&Kch, g_Kch);
    cudaGetSymbolAddress((void**)&Vhh, g_Vhh);
    cudaGetSymbolAddress((void**)&Cth, g_Cth);
    cudaGetSymbolAddress((void**)&Vch, g_Vch);
    cudaGetSymbolAddress((void**)&bhp, g_bh2);
    cudaGetSymbolAddress((void**)&bcp, g_bc2);
    cudaGetSymbolAddress((void**)&Xh,  g_Xh);
    cudaGetSymbolAddress((void**)&Yp,  g_Y);

    cudaFuncSetAttribute(attn2, cudaFuncAttributeMaxDynamicSharedMemorySize,
                         AT_BYTES);

    // --- prep: conversions + attention bias, one launch ---
    CvtArgs ca;
    ca.seg[0]  = {inputs,      inh, (B_ * S_ * HID_) / 4, 1.f};
    ca.seg[1]  = {hot_keys,    hkh, (HOT_ * HID_) / 4, 1.f};
    ca.seg[2]  = {hot_values,  hvh, (HOT_ * HID_) / 4, 1.f};
    ca.seg[3]  = {cold_keys,   ckh, (COLD_ * HID_) / 4, 1.f};
    ca.seg[4]  = {cold_values, cvh, (COLD_ * HID_) / 4, 1.f};
    ca.seg[5]  = {Wq, Wqh, (HID_ * HID_) / 4, K1_};
    ca.seg[6]  = {Wk, Wkh, (HID_ * HID_) / 4, 1.f};
    ca.seg[7]  = {Wv, Wvh, (HID_ * HID_) / 4, 1.f};
    ca.seg[8]  = {Wo, Woh, (HID_ * HID_) / 4, 1.f};
    ca.seg[9]  = {Wc, Wch, (HID_ * COMP_) / 4, 1.f};
    ca.seg[10] = {Wd, Wdh, (COMP_ * HID_) / 4, 1.f};
    ca.ha = hot_age;  ca.hc = hot_access;
    ca.ca = cold_age; ca.cc = cold_access;
    ca.bh = bhp; ca.bc = bcp;
    int total4 = HOT_ / 4 + COLD_ / 4;
    for (int i = 0; i < 11; i++) total4 += ca.seg[i].n4;
    prep_cvt<<<(total4 + 255) / 256, 256>>>(ca);

    // --- projections (128-row tiles, 544 CTAs — measured best) ---
    ProjArgsH pa;
    pa.inh = inh; pa.hkh = hkh; pa.ckh = ckh; pa.hvh = hvh; pa.cvh = cvh;
    pa.Wqh = Wqh; pa.Wkh = Wkh; pa.Wvh = Wvh; pa.Wch = Wch;
    pa.bq = bq; pa.bk = bk; pa.bv = bv; pa.bc = bc;
    pa.Q = Qh; pa.Kh = Khh; pa.Kc = Kch; pa.Vh = Vhh; pa.Ct = Cth;
    proj_fused<<<544, 256>>>(pa);

    // --- Vcold = Ctmp @ Wd + bd (64-row tiles, 384 CTAs — measured best) ---
    gemm_one64<__half><<<384, 256>>>(Cth, Wdh, bd, 1.f, Vch, 1024, 512, 8);

    // --- fused two-tier attention (frozen) ---
    dim3 agrid(S_ / 128, NH_, B_);
    attn2<<<agrid, 128, AT_BYTES>>>(Qh, Khh, Vhh, Kch, Vch, bhp, bcp, Xh);

    // --- Y = X @ Wo + 2*bo (64-row tiles, 256 CTAs) ---
    gemm_one64<float><<<256, 256>>>(Xh, Woh, bo, 2.f, Yp, 1024, 1024, 8);

    ln_kernel<<<B_ * S_, 256>>>(Yp, gamma, beta, out);
}

// round 17
// speedup vs baseline: 1.1124x; 1.0554x over previous
#include <cuda_runtime.h>
#include <cuda_fp16.h>
#include <math.h>
#include <stdint.h>

#define B_    2
#define S_    1024
#define HID_  1024
#define NH_   16
#define HD_   64
#define HOT_  1024
#define COLD_ 3072
#define COMP_ 512
#define EPS_  1e-5f

// ---- async copy / ldmatrix helpers (compute_80-level PTX) ----
__device__ __forceinline__ uint32_t s2u(const void* p) {
    return (uint32_t)__cvta_generic_to_shared(p);
}
#define CP16(d, s) asm volatile("cp.async.cg.shared.global [%0], [%1], 16;" :: "r"(d), "l"(s))
#define CPC()      asm volatile("cp.async.commit_group;" ::: "memory")
#define CPW(n)     asm volatile("cp.async.wait_group %0;" :: "n"(n) : "memory")

__device__ __forceinline__ void ldsm4(uint32_t r[4], uint32_t a) {
    asm volatile("ldmatrix.sync.aligned.m8n8.x4.shared.b16 {%0,%1,%2,%3}, [%4];"
                 : "=r"(r[0]), "=r"(r[1]), "=r"(r[2]), "=r"(r[3]) : "r"(a));
}
__device__ __forceinline__ void ldsm4t(uint32_t r[4], uint32_t a) {
    asm volatile("ldmatrix.sync.aligned.m8n8.x4.trans.shared.b16 {%0,%1,%2,%3}, [%4];"
                 : "=r"(r[0]), "=r"(r[1]), "=r"(r[2]), "=r"(r[3]) : "r"(a));
}
__device__ __forceinline__ void mma_f16(float c[4],
    uint32_t a0, uint32_t a1, uint32_t a2, uint32_t a3,
    uint32_t b0, uint32_t b1)
{
    asm volatile(
        "mma.sync.aligned.m16n8k16.row.col.f32.f16.f16.f32 "
        "{%0,%1,%2,%3}, {%4,%5,%6,%7}, {%8,%9}, {%0,%1,%2,%3};"
        : "+f"(c[0]), "+f"(c[1]), "+f"(c[2]), "+f"(c[3])
        : "r"(a0), "r"(a1), "r"(a2), "r"(a3), "r"(b0), "r"(b1));
}
__device__ __forceinline__ uint32_t pkh2(float a, float b) {
    __half2 h = __floats2half2_rn(a, b);
    return *(uint32_t*)&h;
}
#define HADD2(d, a, b) asm("add.rn.f16x2 %0,%1,%2;" : "=r"(d) : "r"(a), "r"(b))
#define EX2H2(d, a)    asm("ex2.approx.f16x2 %0,%1;" : "=r"(d) : "r"(a))

#define K1_ 0.18033688011112042f   // 0.125 * log2(e)

// ---- scratch (half pipeline) ----
__device__ __half g_inh[B_ * S_ * HID_];
__device__ __half g_hkh[HOT_ * HID_];
__device__ __half g_hvh[HOT_ * HID_];
__device__ __half g_ckh[COLD_ * HID_];
__device__ __half g_cvh[COLD_ * HID_];
__device__ __half g_Wqh[HID_ * HID_];   // pre-scaled by K1
__device__ __half g_Wkh[HID_ * HID_];
__device__ __half g_Wvh[HID_ * HID_];
__device__ __half g_Woh[HID_ * HID_];
__device__ __half g_Wch[HID_ * COMP_];
__device__ __half g_Wdh[COMP_ * HID_];
__device__ __half g_Qh[B_ * S_ * HID_];
__device__ __half g_Khh[HOT_ * HID_];
__device__ __half g_Kch[COLD_ * HID_];
__device__ __half g_Vhh[HOT_ * HID_];
__device__ __half g_Cth[COLD_ * COMP_];
__device__ __half g_Vch[COLD_ * HID_];
__device__ __half g_bh2[HOT_];
__device__ __half g_bc2[COLD_];
__device__ __half g_Xh[B_ * S_ * HID_];
__device__ float  g_Y[B_ * S_ * HID_];

// ============================================================
// prep: fp32 -> fp16 conversion of inputs + weights (w/ scale)
// + attention bias precompute, all in ONE launch
// ============================================================
struct CvtSeg { const float* s; __half* d; int n4; float scl; };
struct CvtArgs {
    CvtSeg seg[11];
    const float *ha, *hc, *ca, *cc;
    __half *bh, *bc;
};

__global__ __launch_bounds__(256) void prep_cvt(CvtArgs a)
{
    const float L2E = 1.4426950408889634f;
    int idx = blockIdx.x * 256 + threadIdx.x;
    #pragma unroll
    for (int i = 0; i < 11; i++) {
        if (idx < a.seg[i].n4) {
            float4 v = ((const float4*)a.seg[i].s)[idx];
            float s = a.seg[i].scl;
            uint2 u = {pkh2(v.x * s, v.y * s), pkh2(v.z * s, v.w * s)};
            ((uint2*)a.seg[i].d)[idx] = u;
            return;
        }
        idx -= a.seg[i].n4;
    }
    if (idx < HOT_ / 4) {
        float4 va = ((const float4*)a.ha)[idx];
        float4 vc = ((const float4*)a.hc)[idx];
        uint2 u = {pkh2(fmaf(-0.1f, va.x, 0.05f * vc.x) * L2E,
                        fmaf(-0.1f, va.y, 0.05f * vc.y) * L2E),
                   pkh2(fmaf(-0.1f, va.z, 0.05f * vc.z) * L2E,
                        fmaf(-0.1f, va.w, 0.05f * vc.w) * L2E)};
        ((uint2*)a.bh)[idx] = u;
        return;
    }
    idx -= HOT_ / 4;
    if (idx < COLD_ / 4) {
        float4 va = ((const float4*)a.ca)[idx];
        float4 vc = ((const float4*)a.cc)[idx];
        uint2 u = {pkh2(fmaf(-0.1f, va.x, 0.05f * vc.x) * L2E,
                        fmaf(-0.1f, va.y, 0.05f * vc.y) * L2E),
                   pkh2(fmaf(-0.1f, va.z, 0.05f * vc.z) * L2E,
                        fmaf(-0.1f, va.w, 0.05f * vc.w) * L2E)};
        ((uint2*)a.bc)[idx] = u;
    }
}

// ============================================================
// store helpers
// ============================================================
__device__ __forceinline__ void st2(__half* C, size_t off, float a, float b) {
    *(__half2*)(C + off) = __floats2half2_rn(a, b);
}
__device__ __forceinline__ void st2(float* C, size_t off, float a, float b) {
    *(float2*)(C + off) = make_float2(a, b);
}

// ============================================================
// GEMM tile A: 128x128x16 4-stage (best for proj)
// ============================================================
__device__ __forceinline__ void g_fill128(
    uint32_t asB, uint32_t bsB, int st, int k0,
    const __half* __restrict__ A, const __half* __restrict__ W,
    int N, int K, int bm, int bn, int tid)
{
    int row = tid >> 1, ch = tid & 1;
    CP16(asB + st * 6144 + row * 48 + ch * 16,
         A + (size_t)(bm + row) * K + k0 + ch * 8);
    int kr = tid >> 4, bc = tid & 15;
    CP16(bsB + st * 4352 + kr * 272 + bc * 16,
         W + (size_t)(k0 + kr) * N + bn + bc * 8);
}

template <typename OT>
__device__ __forceinline__ void gemm_tile128(
    const __half* __restrict__ A, const __half* __restrict__ W,
    const float* __restrict__ bias, float bscale, OT* __restrict__ C,
    int N, int K, int bm, int bn)
{
    __shared__ __align__(16) __half As[4][128 * 24];
    __shared__ __align__(16) __half Bs[4][16 * 136];
    const uint32_t asB = s2u(&As[0][0]);
    const uint32_t bsB = s2u(&Bs[0][0]);

    const int tid = threadIdx.x;
    const int wrp = tid >> 5, lane = tid & 31;
    const int lg = lane >> 2, lc = lane & 3;
    const int wm = (wrp & 3) * 32;
    const int wn = (wrp >> 2) * 64;
    const int kt = K >> 4;

    #pragma unroll
    for (int s = 0; s < 3; s++) {
        g_fill128(asB, bsB, s, s * 16, A, W, N, K, bm, bn, tid);
        CPC();
    }

    float acc[16][4];
    #pragma unroll
    for (int i = 0; i < 16; i++)
        #pragma unroll
        for (int j = 0; j < 4; j++) acc[i][j] = 0.f;

    for (int k = 0; k < kt; k++) {
        CPW(2);
        __syncthreads();
        const int st = k & 3;
        if (k + 3 < kt)
            g_fill128(asB, bsB, (k + 3) & 3, (k + 3) * 16, A, W, N, K, bm, bn, tid);
        CPC();

        const uint32_t aB = asB + st * 6144;
        const uint32_t bB = bsB + st * 4352;
        uint32_t af[2][4], bf[4][4];
        #pragma unroll
        for (int mt = 0; mt < 2; mt++)
            ldsm4(af[mt], aB + (wm + mt * 16 + (lane & 15)) * 48 + (lane >> 4) * 16);
        #pragma unroll
        for (int nt2 = 0; nt2 < 4; nt2++)
            ldsm4t(bf[nt2], bB + (lane & 15) * 272 + wn * 2 + nt2 * 32 + (lane >> 4) * 16);

        #pragma unroll
        for (int mt = 0; mt < 2; mt++)
            #pragma unroll
            for (int nt = 0; nt < 8; nt++)
                mma_f16(acc[mt * 8 + nt],
                        af[mt][0], af[mt][1], af[mt][2], af[mt][3],
                        bf[nt >> 1][(nt & 1) * 2], bf[nt >> 1][(nt & 1) * 2 + 1]);
    }

    #pragma unroll
    for (int nt = 0; nt < 8; nt++) {
        int col = bn + wn + nt * 8 + 2 * lc;
        float2 bv = *(const float2*)(bias + col);
        bv.x *= bscale; bv.y *= bscale;
        #pragma unroll
        for (int mt = 0; mt < 2; mt++) {
            float* c = acc[mt * 8 + nt];
            int row0 = bm + wm + mt * 16 + lg;
            st2(C, (size_t)row0 * N + col, c[0] + bv.x, c[1] + bv.y);
            st2(C, (size_t)(row0 + 8) * N + col, c[2] + bv.x, c[3] + bv.y);
        }
    }
}

// ============================================================
// GEMM tile B: 64x128x16 4-stage (best for Wd/Wo)
// ============================================================
#define GA_ST 3072
#define GB_ST 4352

__device__ __forceinline__ void g_fill64(
    uint32_t asB, uint32_t bsB, int st, int k0,
    const __half* __restrict__ A, const __half* __restrict__ W,
    int N, int K, int bm, int bn, int tid)
{
    if (tid < 128) {
        int row = tid >> 1, ch = tid & 1;
        CP16(asB + st * GA_ST + row * 48 + ch * 16,
             A + (size_t)(bm + row) * K + k0 + ch * 8);
    }
    int kr = tid >> 4, bc = tid & 15;
    CP16(bsB + st * GB_ST + kr * 272 + bc * 16,
         W + (size_t)(k0 + kr) * N + bn + bc * 8);
}

template <typename OT>
__device__ __forceinline__ void gemm_tile64(
    const __half* __restrict__ A, const __half* __restrict__ W,
    const float* __restrict__ bias, float bscale, OT* __restrict__ C,
    int N, int K, int bm, int bn)
{
    __shared__ __align__(16) char As[4 * GA_ST];
    __shared__ __align__(16) char Bs[4 * GB_ST];
    const uint32_t asB = s2u(As);
    const uint32_t bsB = s2u(Bs);

    const int tid = threadIdx.x;
    const int wrp = tid >> 5, lane = tid & 31;
    const int lg = lane >> 2, lc = lane & 3;
    const int wm = (wrp & 1) * 32;
    const int wn = (wrp >> 1) * 32;
    const int kt = K >> 4;

    #pragma unroll
    for (int s = 0; s < 3; s++) {
        g_fill64(asB, bsB, s, s * 16, A, W, N, K, bm, bn, tid);
        CPC();
    }

    float acc[8][4];
    #pragma unroll
    for (int i = 0; i < 8; i++)
        #pragma unroll
        for (int j = 0; j < 4; j++) acc[i][j] = 0.f;

    for (int k = 0; k < kt; k++) {
        CPW(2);
        __syncthreads();
        const int st = k & 3;
        if (k + 3 < kt)
            g_fill64(asB, bsB, (k + 3) & 3, (k + 3) * 16, A, W, N, K, bm, bn, tid);
        CPC();

        const uint32_t aB = asB + st * GA_ST;
        const uint32_t bB = bsB + st * GB_ST;
        uint32_t af[2][4], bf[2][4];
        #pragma unroll
        for (int mt = 0; mt < 2; mt++)
            ldsm4(af[mt], aB + (wm + mt * 16 + (lane & 15)) * 48 + (lane >> 4) * 16);
        #pragma unroll
        for (int nt2 = 0; nt2 < 2; nt2++)
            ldsm4t(bf[nt2], bB + (lane & 15) * 272 + wn * 2 + nt2 * 32 + (lane >> 4) * 16);

        #pragma unroll
        for (int mt = 0; mt < 2; mt++)
            #pragma unroll
            for (int nt = 0; nt < 4; nt++)
                mma_f16(acc[mt * 4 + nt],
                        af[mt][0], af[mt][1], af[mt][2], af[mt][3],
                        bf[nt >> 1][(nt & 1) * 2], bf[nt >> 1][(nt & 1) * 2 + 1]);
    }

    #pragma unroll
    for (int nt = 0; nt < 4; nt++) {
        int col = bn + wn + nt * 8 + 2 * lc;
        float2 bv = *(const float2*)(bias + col);
        bv.x *= bscale; bv.y *= bscale;
        #pragma unroll
        for (int mt = 0; mt < 2; mt++) {
            float* c = acc[mt * 4 + nt];
            int row0 = bm + wm + mt * 16 + lg;
            st2(C, (size_t)row0 * N + col, c[0] + bv.x, c[1] + bv.y);
            st2(C, (size_t)(row0 + 8) * N + col, c[2] + bv.x, c[3] + bv.y);
        }
    }
}

struct ProjArgsH {
    const __half *inh, *hkh, *ckh, *hvh, *cvh;
    const __half *Wqh, *Wkh, *Wvh, *Wch;
    const float *bq, *bk, *bv, *bc;
    __half *Q, *Kh, *Kc, *Vh, *Ct;
};

__global__ __launch_bounds__(256, 2) void proj_fused(ProjArgsH p)
{
    const int bid = blockIdx.x;
    const __half *A, *W; const float* bias; __half* C;
    int N = 1024, nb = 8, base;
    float bsc = 1.f;
    if (bid < 128)      { A = p.inh; W = p.Wqh; bias = p.bq; C = p.Q;  base = 0; bsc = K1_; }
    else if (bid < 192) { A = p.hkh; W = p.Wkh; bias = p.bk; C = p.Kh; base = 128; }
    else if (bid < 384) { A = p.ckh; W = p.Wkh; bias = p.bk; C = p.Kc; base = 192; }
    else if (bid < 448) { A = p.hvh; W = p.Wvh; bias = p.bv; C = p.Vh; base = 384; }
    else                { A = p.cvh; W = p.Wch; bias = p.bc; C = p.Ct; base = 448; N = 512; nb = 4; }
    const int loc = bid - base;
    gemm_tile128(A, W, bias, bsc, C, N, 1024, (loc / nb) * 128, (loc % nb) * 128);
}

template <typename OT>
__global__ __launch_bounds__(256, 3) void gemm_one64(
    const __half* __restrict__ A, const __half* __restrict__ W,
    const float* __restrict__ bias, float bscale, OT* __restrict__ C,
    int N, int K, int nb)
{
    const int loc = blockIdx.x;
    gemm_tile64(A, W, bias, bscale, C, N, K, (loc / nb) * 64, (loc % nb) * 128);
}

// ============================================================
// Fused two-tier attention. R16 structure; La ones-mma replaced
// with f16x2 scalar sums (tensor work -11%, FMA pipe absorbs it).
// ============================================================
#define AT_K(s)  (18432 + (s) * 18688)
#define AT_V(s)  (AT_K(s) + 9216)
#define AT_BB(s) (AT_V(s) + 9216)
#define AT_BYTES (18432 + 2 * 18688)

#define NCH  ((HOT_ + COLD_) / 64)   // 64
#define HCH  (HOT_ / 64)             // 16

__device__ __forceinline__ void a_fill(
    uint32_t smb, int st,
    const __half* __restrict__ Kt, const __half* __restrict__ Vt,
    const __half* __restrict__ bias, int c0, int h, int tid)
{
    const uint32_t kB = smb + AT_K(st);
    const uint32_t vB = smb + AT_V(st);
    #pragma unroll
    for (int i = 0; i < 4; i++) {
        int lin = tid + i * 128;
        int r = lin >> 3, ch = lin & 7;
        size_t g = (size_t)(c0 + r) * HID_ + (size_t)h * HD_ + ch * 8;
        CP16(kB + r * 144 + ch * 16, Kt + g);
        CP16(vB + r * 144 + ch * 16, Vt + g);
    }
    if (tid < 8) CP16(smb + AT_BB(st) + tid * 16, bias + c0 + tid * 8);
}

__global__ __launch_bounds__(128, 2) void attn2(
    const __half* __restrict__ Q,
    const __half* __restrict__ Kh, const __half* __restrict__ Vh,
    const __half* __restrict__ Kc, const __half* __restrict__ Vc,
    const __half* __restrict__ bh, const __half* __restrict__ bc,
    __half* __restrict__ X)
{
    extern __shared__ char smc[];
    const uint32_t smb = s2u(smc);

    const int tid  = threadIdx.x;
    const int w    = tid >> 5;
    const int lane = tid & 31;
    const int lg   = lane >> 2;
    const int lc   = lane & 3;

    const int s0 = blockIdx.x * 128;
    const int h  = blockIdx.y;
    const int b  = blockIdx.z;
    const size_t qgbase = ((size_t)b * S_ + s0) * HID_ + (size_t)h * HD_;

    #pragma unroll
    for (int i = 0; i < 8; i++) {
        int lin = tid + i * 128;
        int r = lin >> 3, ch = lin & 7;
        CP16(smb + r * 144 + ch * 16, Q + qgbase + (size_t)r * HID_ + ch * 8);
    }
    a_fill(smb, 0, Kh, Vh, bh, 0, h, tid);
    CPC();

    float O[2][8][4];
    float lsum[2][2];        // [mt][row: lg, lg+8]
    #pragma unroll
    for (int mt = 0; mt < 2; mt++) {
        lsum[mt][0] = lsum[mt][1] = 0.f;
        #pragma unroll
        for (int nt = 0; nt < 8; nt++)
            #pragma unroll
            for (int j = 0; j < 4; j++) O[mt][nt][j] = 0.f;
    }

    for (int gc = 0; gc < NCH; gc++) {
        const int st = gc & 1;
        CPW(0);
        __syncthreads();

        if (gc + 1 < NCH) {
            int n = gc + 1;
            bool t1 = n >= HCH;
            int cc = t1 ? n - HCH : n;
            a_fill(smb, n & 1, t1 ? Kc : Kh, t1 ? Vc : Vh,
                   t1 ? bc : bh, cc * 64, h, tid);
        }
        CPC();

        const uint32_t kB = smb + AT_K(st);
        const uint32_t vB = smb + AT_V(st);
        const uint32_t* biasS = (const uint32_t*)(smc + AT_BB(st));

        // ---- S = Q @ K^T  (Q pre-scaled by K1) ----
        float sc[2][8][4];
        #pragma unroll
        for (int mt = 0; mt < 2; mt++)
            #pragma unroll
            for (int nt = 0; nt < 8; nt++)
                #pragma unroll
                for (int j = 0; j < 4; j++) sc[mt][nt][j] = 0.f;

        #pragma unroll
        for (int kks = 0; kks < 4; kks++) {
            uint32_t aq[2][4];
            #pragma unroll
            for (int mt = 0; mt < 2; mt++)
                ldsm4(aq[mt], smb + (w * 32 + mt * 16 + (lane & 15)) * 144
                              + kks * 32 + (lane >> 4) * 16);
            #pragma unroll
            for (int nt2 = 0; nt2 < 4; nt2++) {
                uint32_t bk[4];
                ldsm4(bk, kB + (nt2 * 16 + (lane & 7) + ((lane >> 4) << 3)) * 144
                          + kks * 32 + ((lane >> 3) & 1) * 16);
                #pragma unroll
                for (int mt = 0; mt < 2; mt++) {
                    mma_f16(sc[mt][nt2 * 2],     aq[mt][0], aq[mt][1], aq[mt][2], aq[mt][3], bk[0], bk[1]);
                    mma_f16(sc[mt][nt2 * 2 + 1], aq[mt][0], aq[mt][1], aq[mt][2], aq[mt][3], bk[2], bk[3]);
                }
            }
        }

        // ---- softmax + half2 row-sum accumulation (no La-mma) ----
        uint32_t pa[2][4][4];
        #pragma unroll
        for (int mt = 0; mt < 2; mt++) {
            uint32_t s0acc = 0u, s1acc = 0u;     // half2 zeros
            #pragma unroll
            for (int nt = 0; nt < 8; nt++) {
                uint32_t bp = biasS[nt * 4 + lc];
                uint32_t u0 = pkh2(sc[mt][nt][0], sc[mt][nt][1]);
                uint32_t u1 = pkh2(sc[mt][nt][2], sc[mt][nt][3]);
                HADD2(u0, u0, bp);
                HADD2(u1, u1, bp);
                EX2H2(u0, u0);
                EX2H2(u1, u1);
                HADD2(s0acc, s0acc, u0);         // row lg
                HADD2(s1acc, s1acc, u1);         // row lg+8
                int j = nt >> 1;
                if ((nt & 1) == 0) { pa[mt][j][0] = u0; pa[mt][j][1] = u1; }
                else               { pa[mt][j][2] = u0; pa[mt][j][3] = u1; }
            }
            float2 f0 = __half22float2(*(__half2*)&s0acc);
            float2 f1 = __half22float2(*(__half2*)&s1acc);
            lsum[mt][0] += f0.x + f0.y;
            lsum[mt][1] += f1.x + f1.y;
        }

        // ---- O += P @ V ----
        #pragma unroll
        for (int kks = 0; kks < 4; kks++) {
            #pragma unroll
            for (int nt2 = 0; nt2 < 4; nt2++) {
                uint32_t bv[4];
                ldsm4t(bv, vB + (kks * 16 + (lane & 15)) * 144
                           + nt2 * 32 + (lane >> 4) * 16);
                #pragma unroll
                for (int mt = 0; mt < 2; mt++) {
                    mma_f16(O[mt][nt2 * 2],     pa[mt][kks][0], pa[mt][kks][1], pa[mt][kks][2], pa[mt][kks][3], bv[0], bv[1]);
                    mma_f16(O[mt][nt2 * 2 + 1], pa[mt][kks][0], pa[mt][kks][1], pa[mt][kks][2], pa[mt][kks][3], bv[2], bv[3]);
                }
            }
        }

        // ---- tier finalize ----
        if (gc == HCH - 1 || gc == NCH - 1) {
            const int tier = (gc != HCH - 1);
            #pragma unroll
            for (int mt = 0; mt < 2; mt++) {
                #pragma unroll
                for (int hh = 0; hh < 2; hh++) {
                    lsum[mt][hh] += __shfl_xor_sync(0xffffffffu, lsum[mt][hh], 1);
                    lsum[mt][hh] += __shfl_xor_sync(0xffffffffu, lsum[mt][hh], 2);
                }
                float inv0 = 1.f / lsum[mt][0];
                float inv1 = 1.f / lsum[mt][1];
                size_t r0 = qgbase + (size_t)(w * 32 + mt * 16 + lg) * HID_ + 2 * lc;
                size_t r1 = r0 + 8 * HID_;
                #pragma unroll
                for (int nt = 0; nt < 8; nt++) {
                    float o0x = O[mt][nt][0] * inv0, o0y = O[mt][nt][1] * inv0;
                    float o1x = O[mt][nt][2] * inv1, o1y = O[mt][nt][3] * inv1;
                    if (tier) {
                        float2 f0 = __half22float2(*(__half2*)(X + r0 + nt * 8));
                        float2 f1 = __half22float2(*(__half2*)(X + r1 + nt * 8));
                        o0x += f0.x; o0y += f0.y;
                        o1x += f1.x; o1y += f1.y;
                    }
                    *(__half2*)(X + r0 + nt * 8) = __floats2half2_rn(o0x, o0y);
                    *(__half2*)(X + r1 + nt * 8) = __floats2half2_rn(o1x, o1y);
                }
                lsum[mt][0] = lsum[mt][1] = 0.f;
                #pragma unroll
                for (int nt = 0; nt < 8; nt++)
                    #pragma unroll
                    for (int j = 0; j < 4; j++) O[mt][nt][j] = 0.f;
            }
        }
    }
}

// ============================================================
// LayerNorm
// ============================================================
__global__ __launch_bounds__(256) void ln_kernel(
    const float* __restrict__ Y, const float* __restrict__ gamma,
    const float* __restrict__ beta, float* __restrict__ out)
{
    __shared__ float red[16];
    const int row = blockIdx.x;
    const int tid = threadIdx.x;
    const float* y = Y + (size_t)row * HID_;

    float4 v = *(const float4*)(y + tid * 4);
    float sum = v.x + v.y + v.z + v.w;
    float sq  = v.x * v.x + v.y * v.y + v.z * v.z + v.w * v.w;
    #pragma unroll
    for (int o = 16; o > 0; o >>= 1) {
        sum += __shfl_xor_sync(0xffffffffu, sum, o);
        sq  += __shfl_xor_sync(0xffffffffu, sq, o);
    }
    if ((tid & 31) == 0) { red[tid >> 5] = sum; red[8 + (tid >> 5)] = sq; }
    __syncthreads();
    if (tid < 32) {
        float s = (tid < 8) ? red[tid] : 0.f;
        float q = (tid < 8) ? red[8 + tid] : 0.f;
        #pragma unroll
        for (int o = 4; o > 0; o >>= 1) {
            s += __shfl_xor_sync(0xffffffffu, s, o);
            q += __shfl_xor_sync(0xffffffffu, q, o);
        }
        if (tid == 0) { red[0] = s; red[1] = q; }
    }
    __syncthreads();
    float mu   = red[0] * (1.f / HID_);
    float var  = red[1] * (1.f / HID_) - mu * mu;
    float rstd = rsqrtf(var + EPS_);

    float4 g  = *(const float4*)(gamma + tid * 4);
    float4 bt = *(const float4*)(beta + tid * 4);
    float4 o;
    o.x = (v.x - mu) * rstd * g.x + bt.x;
    o.y = (v.y - mu) * rstd * g.y + bt.y;
    o.z = (v.z - mu) * rstd * g.z + bt.z;
    o.w = (v.w - mu) * rstd * g.w + bt.w;
    *(float4*)(out + (size_t)row * HID_ + tid * 4) = o;
}

// ============================================================
extern "C" void kernel_launch(void* const* d_in, const int* in_sizes, int n_in,
                              void* d_out, int out_size)
{
    const float* inputs      = (const float*)d_in[0];
    const float* hot_keys    = (const float*)d_in[1];
    const float* hot_values  = (const float*)d_in[2];
    const float* hot_age     = (const float*)d_in[3];
    const float* hot_access  = (const float*)d_in[4];
    const float* cold_keys   = (const float*)d_in[5];
    const float* cold_values = (const float*)d_in[6];
    const float* cold_age    = (const float*)d_in[7];
    const float* cold_access = (const float*)d_in[8];
    const float* Wq = (const float*)d_in[9];
    const float* bq = (const float*)d_in[10];
    const float* Wk = (const float*)d_in[11];
    const float* bk = (const float*)d_in[12];
    const float* Wv = (const float*)d_in[13];
    const float* bv = (const float*)d_in[14];
    const float* Wo = (const float*)d_in[15];
    const float* bo = (const float*)d_in[16];
    const float* Wc = (const float*)d_in[17];
    const float* bc = (const float*)d_in[18];
    const float* Wd = (const float*)d_in[19];
    const float* bd = (const float*)d_in[20];
    const float* gamma = (const float*)d_in[21];
    const float* beta  = (const float*)d_in[22];
    float* out = (float*)d_out;

    __half *inh, *hkh, *hvh, *ckh, *cvh;
    __half *Wqh, *Wkh, *Wvh, *Woh, *Wch, *Wdh;
    __half *Qh, *Khh, *Kch, *Vhh, *Cth, *Vch, *Xh;
    __half *bhp, *bcp;
    float *Yp;
    cudaGetSymbolAddress((void**)&inh, g_inh);
    cudaGetSymbolAddress((void**)&hkh, g_hkh);
    cudaGetSymbolAddress((void**)&hvh, g_hvh);
    cudaGetSymbolAddress((void**)&ckh, g_ckh);
    cudaGetSymbolAddress((void**)&cvh, g_cvh);
    cudaGetSymbolAddress((void**)&Wqh, g_Wqh);
    cudaGetSymbolAddress((void**)&Wkh, g_Wkh);
    cudaGetSymbolAddress((void**)&Wvh, g_Wvh);
    cudaGetSymbolAddress((void**)&Woh, g_Woh);
    cudaGetSymbolAddress((void**)&Wch, g_Wch);
    cudaGetSymbolAddress((void**)&Wdh, g_Wdh);
    cudaGetSymbolAddress((void**)&Qh,  g_Qh);
    cudaGetSymbolAddress((void**)&Khh, g_Khh);
    cudaGetSymbolAddress((void**)&Kch, g_Kch);
    cudaGetSymbolAddress((void**)&Vhh, g_Vhh);
    cudaGetSymbolAddress((void**)&Cth, g_Cth);
    cudaGetSymbolAddress((void**)&Vch, g_Vch);
    cudaGetSymbolAddress((void**)&bhp, g_bh2);
    cudaGetSymbolAddress((void**)&bcp, g_bc2);
    cudaGetSymbolAddress((void**)&Xh,  g_Xh);
    cudaGetSymbolAddress((void**)&Yp,  g_Y);

    cudaFuncSetAttribute(attn2, cudaFuncAttributeMaxDynamicSharedMemorySize,
                         AT_BYTES);

    // --- prep: conversions + attention bias, one launch ---
    CvtArgs ca;
    ca.seg[0]  = {inputs,      inh, (B_ * S_ * HID_) / 4, 1.f};
    ca.seg[1]  = {hot_keys,    hkh, (HOT_ * HID_) / 4, 1.f};
    ca.seg[2]  = {hot_values,  hvh, (HOT_ * HID_) / 4, 1.f};
    ca.seg[3]  = {cold_keys,   ckh, (COLD_ * HID_) / 4, 1.f};
    ca.seg[4]  = {cold_values, cvh, (COLD_ * HID_) / 4, 1.f};
    ca.seg[5]  = {Wq, Wqh, (HID_ * HID_) / 4, K1_};
    ca.seg[6]  = {Wk, Wkh, (HID_ * HID_) / 4, 1.f};
    ca.seg[7]  = {Wv, Wvh, (HID_ * HID_) / 4, 1.f};
    ca.seg[8]  = {Wo, Woh, (HID_ * HID_) / 4, 1.f};
    ca.seg[9]  = {Wc, Wch, (HID_ * COMP_) / 4, 1.f};
    ca.seg[10] = {Wd, Wdh, (COMP_ * HID_) / 4, 1.f};
    ca.ha = hot_age;  ca.hc = hot_access;
    ca.ca = cold_age; ca.cc = cold_access;
    ca.bh = bhp; ca.bc = bcp;
    int total4 = HOT_ / 4 + COLD_ / 4;
    for (int i = 0; i < 11; i++) total4 += ca.seg[i].n4;
    prep_cvt<<<(total4 + 255) / 256, 256>>>(ca);

    // --- projections (128-row tiles, 544 CTAs) ---
    ProjArgsH pa;
    pa.inh = inh; pa.hkh = hkh; pa.ckh = ckh; pa.hvh = hvh; pa.cvh = cvh;
    pa.Wqh = Wqh; pa.Wkh = Wkh; pa.Wvh = Wvh; pa.Wch = Wch;
    pa.bq = bq; pa.bk = bk; pa.bv = bv; pa.bc = bc;
    pa.Q = Qh; pa.Kh = Khh; pa.Kc = Kch; pa.Vh = Vhh; pa.Ct = Cth;
    proj_fused<<<544, 256>>>(pa);

    // --- Vcold = Ctmp @ Wd + bd (64-row tiles) ---
    gemm_one64<__half><<<384, 256>>>(Cth, Wdh, bd, 1.f, Vch, 1024, 512, 8);

    // --- fused two-tier attention ---
    dim3 agrid(S_ / 128, NH_, B_);
    attn2<<<agrid, 128, AT_BYTES>>>(Qh, Khh, Vhh, Kch, Vch, bhp, bcp, Xh);

    // --- Y = X @ Wo + 2*bo (64-row tiles) ---
    gemm_one64<float><<<256, 256>>>(Xh, Woh, bo, 2.f, Yp, 1024, 1024, 8);

    ln_kernel<<<B_ * S_, 256>>>(Yp, gamma, beta, out);
}